// round 12
// baseline (speedup 1.0000x reference)
#include <cuda_runtime.h>
#include <cuda_bf16.h>
#include <cstdint>

// Problem constants (B=8192, D=1024, T=0.5)
#define B_ROWS 8192
#define D_DIM  1024
#define TEMP   0.5f
#define LOG2E  1.44269504088896f
#define NEG2LOG2E (-2.88539008177793f)

#define TS      128                    // tile side
#define NB      (B_ROWS / TS)          // 64
#define NTILES  (NB * (NB + 1) / 2)    // 2080 upper-triangular tiles
#define BK      64                     // bf16 elems per row per stage (=128B)
#define NSTAGE  (D_DIM / BK)           // 16
#define FGRID   32                     // final reduction blocks

// dynamic smem layout (relative to 1024-aligned base)
#define OFF_LABI  0
#define OFF_LABJ  512
#define OFF_ZR    1024
#define OFF_PR    1536
#define OFF_ZC    2048
#define OFF_PC    2560
#define OFF_A     4096                          // 3 x 16KB
#define OFF_B     (OFF_A + 3 * TS * 128)        // 3 x 16KB
#define SMEM_NEED (OFF_B + 3 * TS * 128 + 1024) // ~101KB (2 CTAs/SM: 202<228)

// device scratch (no allocation allowed)
__device__ __nv_bfloat16 g_fb[(size_t)B_ROWS * D_DIM];  // 16 MB normalized bf16
__device__ float g_Z[B_ROWS];
__device__ float g_P[B_ROWS];
__device__ int   g_cnt[128];
__device__ float g_sum;
__device__ float g_cntv;
__device__ unsigned int g_ticket;

// ---------------- helpers ----------------
__device__ __forceinline__ uint32_t smem_u32(const void* p) {
    uint32_t a;
    asm("{ .reg .u64 t; cvta.to.shared.u64 t, %1; cvt.u32.u64 %0, t; }" : "=r"(a) : "l"(p));
    return a;
}
__device__ __forceinline__ void cp16(uint32_t dst, const void* src) {
    asm volatile("cp.async.cg.shared.global [%0], [%1], 16;" :: "r"(dst), "l"(src) : "memory");
}
#define CP_COMMIT() asm volatile("cp.async.commit_group;" ::: "memory")
template <int N> __device__ __forceinline__ void cp_wait() {
    asm volatile("cp.async.wait_group %0;" :: "n"(N) : "memory");
}
__device__ __forceinline__ void ldm_x4(uint32_t* r, uint32_t addr) {
    asm volatile("ldmatrix.sync.aligned.m8n8.x4.shared.b16 {%0,%1,%2,%3}, [%4];"
                 : "=r"(r[0]), "=r"(r[1]), "=r"(r[2]), "=r"(r[3]) : "r"(addr));
}
__device__ __forceinline__ void mma16816(float* d, const uint32_t* a, const uint32_t* b) {
    asm volatile(
        "mma.sync.aligned.m16n8k16.row.col.f32.bf16.bf16.f32 "
        "{%0,%1,%2,%3}, {%4,%5,%6,%7}, {%8,%9}, {%0,%1,%2,%3};"
        : "+f"(d[0]), "+f"(d[1]), "+f"(d[2]), "+f"(d[3])
        : "r"(a[0]), "r"(a[1]), "r"(a[2]), "r"(a[3]), "r"(b[0]), "r"(b[1]));
}
__device__ __forceinline__ float ex2(float x) {
    float y; asm("ex2.approx.ftz.f32 %0, %1;" : "=f"(y) : "f"(x)); return y;
}

// ---------------- small kernels ----------------
// single block: zero label histogram + scalar accumulators
__global__ void init_kernel() {
    int t = threadIdx.x;
    if (t < 128)  g_cnt[t] = 0;
    if (t == 128) { g_sum = 0.f; g_cntv = 0.f; g_ticket = 0u; }
}
// fused: L2-normalize + bf16 quantize + label histogram + Z/P zeroing
__global__ __launch_bounds__(256) void norm_kernel(const float* __restrict__ f,
                                                   const long long* __restrict__ labels) {
    int row = blockIdx.x;
    if (threadIdx.x == 0) {
        atomicAdd(&g_cnt[(int)labels[row] & 127], 1);
        g_Z[row] = 0.f;
        g_P[row] = 0.f;
    }
    const float4* src = (const float4*)(f + (size_t)row * D_DIM);
    float4 v = src[threadIdx.x];
    float ss = v.x * v.x + v.y * v.y + v.z * v.z + v.w * v.w;
    #pragma unroll
    for (int o = 16; o; o >>= 1) ss += __shfl_xor_sync(0xffffffffu, ss, o);
    __shared__ float red[8];
    if ((threadIdx.x & 31) == 0) red[threadIdx.x >> 5] = ss;
    __syncthreads();
    float tot = red[0] + red[1] + red[2] + red[3] + red[4] + red[5] + red[6] + red[7];
    float sc = rsqrtf(fmaxf(tot, 1e-24f));
    __nv_bfloat162* dst = (__nv_bfloat162*)(g_fb + (size_t)row * D_DIM);
    dst[threadIdx.x * 2 + 0] = __nv_bfloat162(__float2bfloat16_rn(v.x * sc), __float2bfloat16_rn(v.y * sc));
    dst[threadIdx.x * 2 + 1] = __nv_bfloat162(__float2bfloat16_rn(v.z * sc), __float2bfloat16_rn(v.w * sc));
}

// ---------------- main fused syrk + supcon epilogue ----------------
__device__ __forceinline__ void load_stage(int st, int buf, int t, int row0, int col0,
                                           uint32_t sb) {
    int kc = st * BK;
    uint32_t abase = sb + OFF_A + buf * (TS * 128);
    uint32_t bbase = sb + OFF_B + buf * (TS * 128);
    #pragma unroll
    for (int i = 0; i < 16; i++) {
        int idx = t + i * 128;        // 0..2047
        int rl  = idx >> 3;           // 0..255
        int ch  = idx & 7;            // 16B chunk within 128B row
        int rr  = rl & 127;
        uint32_t off = (uint32_t)(rr * 128 + ch * 16);
        off ^= (off >> 3) & 0x70;     // SW128
        if (rl < 128) cp16(abase + off, g_fb + (size_t)(row0 + rr) * D_DIM + kc + ch * 8);
        else          cp16(bbase + off, g_fb + (size_t)(col0 + rr) * D_DIM + kc + ch * 8);
    }
}

__global__ __launch_bounds__(128, 2) void gemm_kernel(const long long* __restrict__ labels) {
    extern __shared__ char dsm[];
    uint32_t raw = smem_u32(dsm);
    uint32_t sb  = (raw + 1023) & ~1023u;
    char* s = dsm + (sb - raw);

    int t = threadIdx.x;
    int wid = t >> 5, lane = t & 31;

    // tile decode (bi <= bj)
    int b = blockIdx.x, bi = 0;
    while (b >= NB - bi) { b -= NB - bi; bi++; }
    int bj = bi + b;
    bool diag = (bi == bj);
    int row0 = bi * TS, col0 = bj * TS;

    int*   sLabI = (int*)(s + OFF_LABI);
    int*   sLabJ = (int*)(s + OFF_LABJ);
    float* sZr   = (float*)(s + OFF_ZR);
    float* sPr   = (float*)(s + OFF_PR);
    float* sZc   = (float*)(s + OFF_ZC);
    float* sPc   = (float*)(s + OFF_PC);

    sLabI[t] = (int)labels[row0 + t];
    sLabJ[t] = (int)labels[col0 + t];
    sZr[t] = 0.f; sPr[t] = 0.f; sZc[t] = 0.f; sPc[t] = 0.f;

    // 4 warps, 2x2 grid of 64x64 warp tiles
    int m_off = (wid >> 1) * 64;
    int n_off = (wid & 1) * 64;

    uint32_t aRow[4], aXor[4];
    {
        int r = m_off + (lane & 15);
        #pragma unroll
        for (int mt = 0; mt < 4; mt++) {
            uint32_t rb = (uint32_t)(r + mt * 16) * 128;
            aRow[mt] = rb; aXor[mt] = (rb >> 3) & 0x70;
        }
    }
    uint32_t aK8 = ((lane >> 4) & 1) * 16;   // bytes
    uint32_t bRow[4], bXor[4];
    {
        int n = n_off + (lane & 7) + ((lane >> 4) << 3);
        #pragma unroll
        for (int np = 0; np < 4; np++) {
            uint32_t rb = (uint32_t)(n + np * 16) * 128;
            bRow[np] = rb; bXor[np] = (rb >> 3) & 0x70;
        }
    }
    uint32_t bK8 = ((lane >> 3) & 1) * 16;   // bytes

    float acc[4][8][4];
    #pragma unroll
    for (int mt = 0; mt < 4; mt++)
        #pragma unroll
        for (int nt = 0; nt < 8; nt++)
            #pragma unroll
            for (int k = 0; k < 4; k++) acc[mt][nt][k] = 0.f;

    // 3-buffer, prefetch-depth-1, single-sync pipeline.
    // At iter st: issue st+1 into buf (st+1)%3 BEFORE the wait+barrier.
    // Overwritten buffer aliases (st-2)%3; all warps' stage st-2 reads
    // precede their arrival at barrier st-1, which the issuing warp has
    // passed before this write. Safe.
    load_stage(0, 0, t, row0, col0, sb);
    CP_COMMIT();

    for (int st = 0; st < NSTAGE; st++) {
        if (st + 1 < NSTAGE) {
            load_stage(st + 1, (st + 1) % 3, t, row0, col0, sb);
            CP_COMMIT();
            cp_wait<1>();
        } else {
            cp_wait<0>();
        }
        __syncthreads();   // single barrier per stage

        int buf = st % 3;
        uint32_t aBase = sb + OFF_A + buf * (TS * 128);
        uint32_t bBase = sb + OFF_B + buf * (TS * 128);
        #pragma unroll
        for (int ks = 0; ks < 4; ks++) {
            uint32_t kbA = (uint32_t)(ks * 32) + aK8;
            uint32_t kbB = (uint32_t)(ks * 32) + bK8;
            uint32_t af[4][4], bf[4][4];
            #pragma unroll
            for (int mt = 0; mt < 4; mt++)
                ldm_x4(af[mt], aBase + aRow[mt] + (kbA ^ aXor[mt]));
            #pragma unroll
            for (int np = 0; np < 4; np++)
                ldm_x4(bf[np], bBase + bRow[np] + (kbB ^ bXor[np]));
            #pragma unroll
            for (int mt = 0; mt < 4; mt++) {
                #pragma unroll
                for (int nt = 0; nt < 8; nt++) {
                    const uint32_t* bb = &bf[nt >> 1][(nt & 1) * 2];
                    mma16816(acc[mt][nt], af[mt], bb);
                }
            }
        }
    }

    // ---- epilogue ----
    // value (mt, nt, k): row = m_off + mt*16 + (lane>>2) + ((k>>1)&1)*8
    //                    col = n_off + nt*8  + (lane&3)*2 + (k&1)
    int rbase = m_off + (lane >> 2);
    int cbase = n_off + (lane & 3) * 2;

    int labR[8], labC[16];
    #pragma unroll
    for (int h = 0; h < 8; h++) labR[h] = sLabI[rbase + (h >> 1) * 16 + (h & 1) * 8];
    #pragma unroll
    for (int q = 0; q < 16; q++) labC[q] = sLabJ[cbase + (q >> 1) * 8 + (q & 1)];

    float zrp[8], prp[8], zcp[16], pcp[16];
    #pragma unroll
    for (int h = 0; h < 8; h++) { zrp[h] = 0.f; prp[h] = 0.f; }
    #pragma unroll
    for (int q = 0; q < 16; q++) { zcp[q] = 0.f; pcp[q] = 0.f; }

    #pragma unroll
    for (int mt = 0; mt < 4; mt++) {
        #pragma unroll
        for (int nt = 0; nt < 8; nt++) {
            #pragma unroll
            for (int k = 0; k < 4; k++) {
                int h = mt * 2 + ((k >> 1) & 1);
                int q = nt * 2 + (k & 1);
                int row = rbase + ((k >> 1) & 1) * 8 + mt * 16;
                int col = cbase + (k & 1) + nt * 8;
                float lg = 2.0f * acc[mt][nt][k];
                float e  = ex2(fmaf(lg, LOG2E, NEG2LOG2E));
                bool self = diag && (row == col);
                float ez = self ? 0.f : e;
                bool pos = (!self) && (labR[h] == labC[q]);
                float pz = pos ? lg : 0.f;
                zrp[h] += ez; prp[h] += pz;
                zcp[q] += ez; pcp[q] += pz;
            }
        }
    }

    // row reduce: lanes sharing a row differ in (lane&3)
    #pragma unroll
    for (int h = 0; h < 8; h++) {
        zrp[h] += __shfl_xor_sync(0xffffffffu, zrp[h], 1);
        zrp[h] += __shfl_xor_sync(0xffffffffu, zrp[h], 2);
        prp[h] += __shfl_xor_sync(0xffffffffu, prp[h], 1);
        prp[h] += __shfl_xor_sync(0xffffffffu, prp[h], 2);
        if ((lane & 3) == 0) {
            int row = rbase + (h >> 1) * 16 + (h & 1) * 8;
            atomicAdd(&sZr[row], zrp[h]);
            atomicAdd(&sPr[row], prp[h]);
        }
    }
    // col reduce: lanes sharing a col differ in (lane>>2)
    if (!diag) {
        #pragma unroll
        for (int q = 0; q < 16; q++) {
            zcp[q] += __shfl_xor_sync(0xffffffffu, zcp[q], 4);
            zcp[q] += __shfl_xor_sync(0xffffffffu, zcp[q], 8);
            zcp[q] += __shfl_xor_sync(0xffffffffu, zcp[q], 16);
            pcp[q] += __shfl_xor_sync(0xffffffffu, pcp[q], 4);
            pcp[q] += __shfl_xor_sync(0xffffffffu, pcp[q], 8);
            pcp[q] += __shfl_xor_sync(0xffffffffu, pcp[q], 16);
            if ((lane >> 2) == 0) {
                int col = cbase + (q >> 1) * 8 + (q & 1);
                atomicAdd(&sZc[col], zcp[q]);
                atomicAdd(&sPc[col], pcp[q]);
            }
        }
    }
    __syncthreads();

    atomicAdd(&g_Z[row0 + t], sZr[t]);
    atomicAdd(&g_P[row0 + t], sPr[t]);
    if (!diag) {
        atomicAdd(&g_Z[col0 + t], sZc[t]);
        atomicAdd(&g_P[col0 + t], sPc[t]);
    }
}

// ---------------- per-row loss, parallel reduction + fused scalar write ----------------
__global__ __launch_bounds__(256) void final_partial(const long long* __restrict__ labels,
                                                     float* __restrict__ out) {
    __shared__ float ssum[256];
    __shared__ float scnt[256];
    float sum = 0.f, cnt = 0.f;
    for (int i = blockIdx.x * 256 + threadIdx.x; i < B_ROWS; i += FGRID * 256) {
        int n = g_cnt[(int)labels[i] & 127] - 1;
        if (n > 0) {
            float per = g_P[i] / (float)n - 2.0f - logf(g_Z[i]);
            sum += -TEMP * per;
            cnt += 1.f;
        }
    }
    ssum[threadIdx.x] = sum; scnt[threadIdx.x] = cnt;
    __syncthreads();
    for (int sft = 128; sft; sft >>= 1) {
        if (threadIdx.x < sft) {
            ssum[threadIdx.x] += ssum[threadIdx.x + sft];
            scnt[threadIdx.x] += scnt[threadIdx.x + sft];
        }
        __syncthreads();
    }
    if (threadIdx.x == 0) {
        atomicAdd(&g_sum, ssum[0]);
        atomicAdd(&g_cntv, scnt[0]);
        __threadfence();
        unsigned int ticket = atomicAdd(&g_ticket, 1u);
        if (ticket == FGRID - 1) {
            float total = atomicAdd(&g_sum, 0.f);     // fenced read-through-L2
            float nvald = atomicAdd(&g_cntv, 0.f);
            out[0] = total / fmaxf(nvald, 1.0f);
        }
    }
}

// ---------------------------------------------------------------------------
extern "C" void kernel_launch(void* const* d_in, const int* in_sizes, int n_in,
                              void* d_out, int out_size) {
    const float*     feat   = (const float*)d_in[0];
    const long long* labels = (const long long*)d_in[1];
    float*           out    = (float*)d_out;

    cudaFuncSetAttribute(gemm_kernel, cudaFuncAttributeMaxDynamicSharedMemorySize, SMEM_NEED);

    init_kernel<<<1, 256>>>();
    norm_kernel<<<B_ROWS, 256>>>(feat, labels);
    gemm_kernel<<<NTILES, 128, SMEM_NEED>>>(labels);
    final_partial<<<FGRID, 256>>>(labels, out);
}

// round 13
// speedup vs baseline: 1.0585x; 1.0585x over previous
#include <cuda_runtime.h>
#include <cuda.h>
#include <cuda_bf16.h>
#include <cstdint>

// Problem constants (B=8192, D=1024, T=0.5)
#define B_ROWS 8192
#define D_DIM  1024
#define TEMP   0.5f
#define LOG2E  1.44269504088896f
#define NEG2LOG2E (-2.88539008177793f)

#define TS      128                    // tile side
#define NB      (B_ROWS / TS)          // 64
#define NTILES  (NB * (NB + 1) / 2)    // 2080 upper-triangular tiles
#define BK      64                     // bf16 elems per row per stage (=128B)
#define NSTAGE  (D_DIM / BK)           // 16
#define FGRID   32                     // final reduction blocks
#define STAGE_BYTES (2 * TS * 128)     // A box + B box = 32KB

// dynamic smem layout (relative to 1024-aligned base)
#define OFF_LABI  0
#define OFF_LABJ  512
#define OFF_ZR    1024
#define OFF_PR    1536
#define OFF_ZC    2048
#define OFF_PC    2560
#define OFF_MBAR  3072                         // 2 x 8B mbarriers
#define OFF_A     4096                         // 2 x 16KB
#define OFF_B     (OFF_A + 2 * TS * 128)       // 36864, 2 x 16KB
#define SMEM_NEED (OFF_B + 2 * TS * 128 + 1024)

// device scratch (no allocation allowed)
__device__ __nv_bfloat16 g_fb[(size_t)B_ROWS * D_DIM];  // 16 MB normalized bf16
__device__ float g_Z[B_ROWS];
__device__ float g_P[B_ROWS];
__device__ int   g_cnt[128];
__device__ float g_sum;
__device__ float g_cntv;
__device__ unsigned int g_ticket;

// ---------------- helpers ----------------
__device__ __forceinline__ uint32_t smem_u32(const void* p) {
    uint32_t a;
    asm("{ .reg .u64 t; cvta.to.shared.u64 t, %1; cvt.u32.u64 %0, t; }" : "=r"(a) : "l"(p));
    return a;
}
__device__ __forceinline__ void mbar_init(uint32_t a, uint32_t c) {
    asm volatile("mbarrier.init.shared.b64 [%0], %1;" :: "r"(a), "r"(c) : "memory");
}
__device__ __forceinline__ void mbar_expect_tx(uint32_t a, uint32_t bytes) {
    asm volatile("mbarrier.arrive.expect_tx.shared.b64 _, [%0], %1;"
                 :: "r"(a), "r"(bytes) : "memory");
}
__device__ __forceinline__ void mbar_wait(uint32_t a, uint32_t parity) {
    asm volatile(
        "{\n\t.reg .pred P;\n\t"
        "W_%=:\n\t"
        "mbarrier.try_wait.parity.shared.b64 P, [%0], %1, 0x989680;\n\t"
        "@P bra.uni D_%=;\n\t"
        "bra.uni W_%=;\n\t"
        "D_%=:\n\t}"
        :: "r"(a), "r"(parity) : "memory");
}
__device__ __forceinline__ void tma_load_2d(uint32_t dst, const CUtensorMap* tmap,
                                            int cx, int cy, uint32_t mbar) {
    asm volatile(
        "cp.async.bulk.tensor.2d.shared::cta.global.tile.mbarrier::complete_tx::bytes "
        "[%0], [%1, {%2, %3}], [%4];"
        :: "r"(dst), "l"(tmap), "r"(cx), "r"(cy), "r"(mbar) : "memory");
}
__device__ __forceinline__ void ldm_x4(uint32_t* r, uint32_t addr) {
    asm volatile("ldmatrix.sync.aligned.m8n8.x4.shared.b16 {%0,%1,%2,%3}, [%4];"
                 : "=r"(r[0]), "=r"(r[1]), "=r"(r[2]), "=r"(r[3]) : "r"(addr));
}
__device__ __forceinline__ void mma16816(float* d, const uint32_t* a, const uint32_t* b) {
    asm volatile(
        "mma.sync.aligned.m16n8k16.row.col.f32.bf16.bf16.f32 "
        "{%0,%1,%2,%3}, {%4,%5,%6,%7}, {%8,%9}, {%0,%1,%2,%3};"
        : "+f"(d[0]), "+f"(d[1]), "+f"(d[2]), "+f"(d[3])
        : "r"(a[0]), "r"(a[1]), "r"(a[2]), "r"(a[3]), "r"(b[0]), "r"(b[1]));
}
__device__ __forceinline__ float ex2(float x) {
    float y; asm("ex2.approx.ftz.f32 %0, %1;" : "=f"(y) : "f"(x)); return y;
}

// ---------------- small kernels ----------------
__global__ void init_kernel() {
    int t = threadIdx.x;
    if (t < 128)  g_cnt[t] = 0;
    if (t == 128) { g_sum = 0.f; g_cntv = 0.f; g_ticket = 0u; }
}
// fused: L2-normalize + bf16 quantize + label histogram + Z/P zeroing
__global__ __launch_bounds__(256) void norm_kernel(const float* __restrict__ f,
                                                   const long long* __restrict__ labels) {
    int row = blockIdx.x;
    if (threadIdx.x == 0) {
        atomicAdd(&g_cnt[(int)labels[row] & 127], 1);
        g_Z[row] = 0.f;
        g_P[row] = 0.f;
    }
    const float4* src = (const float4*)(f + (size_t)row * D_DIM);
    float4 v = src[threadIdx.x];
    float ss = v.x * v.x + v.y * v.y + v.z * v.z + v.w * v.w;
    #pragma unroll
    for (int o = 16; o; o >>= 1) ss += __shfl_xor_sync(0xffffffffu, ss, o);
    __shared__ float red[8];
    if ((threadIdx.x & 31) == 0) red[threadIdx.x >> 5] = ss;
    __syncthreads();
    float tot = red[0] + red[1] + red[2] + red[3] + red[4] + red[5] + red[6] + red[7];
    float sc = rsqrtf(fmaxf(tot, 1e-24f));
    __nv_bfloat162* dst = (__nv_bfloat162*)(g_fb + (size_t)row * D_DIM);
    dst[threadIdx.x * 2 + 0] = __nv_bfloat162(__float2bfloat16_rn(v.x * sc), __float2bfloat16_rn(v.y * sc));
    dst[threadIdx.x * 2 + 1] = __nv_bfloat162(__float2bfloat16_rn(v.z * sc), __float2bfloat16_rn(v.w * sc));
}

// ---------------- main fused syrk + supcon epilogue (TMA loads) ----------------
__global__ __launch_bounds__(128, 2) void gemm_kernel(const long long* __restrict__ labels,
                                                      const __grid_constant__ CUtensorMap tmap) {
    extern __shared__ char dsm[];
    uint32_t raw = smem_u32(dsm);
    uint32_t sb  = (raw + 1023) & ~1023u;
    char* s = dsm + (sb - raw);

    int t = threadIdx.x;
    int wid = t >> 5, lane = t & 31;

    // tile decode (bi <= bj)
    int b = blockIdx.x, bi = 0;
    while (b >= NB - bi) { b -= NB - bi; bi++; }
    int bj = bi + b;
    bool diag = (bi == bj);
    int row0 = bi * TS, col0 = bj * TS;

    int*   sLabI = (int*)(s + OFF_LABI);
    int*   sLabJ = (int*)(s + OFF_LABJ);
    float* sZr   = (float*)(s + OFF_ZR);
    float* sPr   = (float*)(s + OFF_PR);
    float* sZc   = (float*)(s + OFF_ZC);
    float* sPc   = (float*)(s + OFF_PC);

    sLabI[t] = (int)labels[row0 + t];
    sLabJ[t] = (int)labels[col0 + t];
    sZr[t] = 0.f; sPr[t] = 0.f; sZc[t] = 0.f; sPc[t] = 0.f;

    uint32_t mb0 = sb + OFF_MBAR, mb1 = sb + OFF_MBAR + 8;
    if (t == 0) { mbar_init(mb0, 1); mbar_init(mb1, 1); }
    __syncthreads();   // mbar init visible before first TMA

    // 4 warps, 2x2 grid of 64x64 warp tiles
    int m_off = (wid >> 1) * 64;
    int n_off = (wid & 1) * 64;

    uint32_t aRow[4], aXor[4];
    {
        int r = m_off + (lane & 15);
        #pragma unroll
        for (int mt = 0; mt < 4; mt++) {
            uint32_t rb = (uint32_t)(r + mt * 16) * 128;
            aRow[mt] = rb; aXor[mt] = (rb >> 3) & 0x70;
        }
    }
    uint32_t aK8 = ((lane >> 4) & 1) * 16;   // bytes
    uint32_t bRow[4], bXor[4];
    {
        int n = n_off + (lane & 7) + ((lane >> 4) << 3);
        #pragma unroll
        for (int np = 0; np < 4; np++) {
            uint32_t rb = (uint32_t)(n + np * 16) * 128;
            bRow[np] = rb; bXor[np] = (rb >> 3) & 0x70;
        }
    }
    uint32_t bK8 = ((lane >> 3) & 1) * 16;   // bytes

    float acc[4][8][4];
    #pragma unroll
    for (int mt = 0; mt < 4; mt++)
        #pragma unroll
        for (int nt = 0; nt < 8; nt++)
            #pragma unroll
            for (int k = 0; k < 4; k++) acc[mt][nt][k] = 0.f;

    // stage 0 into buffer 0
    if (t == 0) {
        mbar_expect_tx(mb0, STAGE_BYTES);
        tma_load_2d(sb + OFF_A, &tmap, 0, row0, mb0);
        tma_load_2d(sb + OFF_B, &tmap, 0, col0, mb0);
    }
    int ph0 = 0, ph1 = 0;

    for (int st = 0; st < NSTAGE; st++) {
        int buf = st & 1;
        // prefetch next stage into the other buffer; trailing __syncthreads of
        // stage st-1 guarantees all warps finished reading it (same as R10).
        if (st + 1 < NSTAGE && t == 0) {
            uint32_t nb = buf ^ 1;
            uint32_t mbn = nb ? mb1 : mb0;
            uint32_t ao = sb + OFF_A + nb * (TS * 128);
            uint32_t bo = sb + OFF_B + nb * (TS * 128);
            int kc = (st + 1) * BK;
            mbar_expect_tx(mbn, STAGE_BYTES);
            tma_load_2d(ao, &tmap, kc, row0, mbn);
            tma_load_2d(bo, &tmap, kc, col0, mbn);
        }
        // wait for current stage's data
        if (buf) { mbar_wait(mb1, ph1); ph1 ^= 1; }
        else     { mbar_wait(mb0, ph0); ph0 ^= 1; }

        uint32_t aBase = sb + OFF_A + buf * (TS * 128);
        uint32_t bBase = sb + OFF_B + buf * (TS * 128);
        #pragma unroll
        for (int ks = 0; ks < 4; ks++) {
            uint32_t kbA = (uint32_t)(ks * 32) + aK8;
            uint32_t kbB = (uint32_t)(ks * 32) + bK8;
            uint32_t af[4][4], bf[4][4];
            #pragma unroll
            for (int mt = 0; mt < 4; mt++)
                ldm_x4(af[mt], aBase + aRow[mt] + (kbA ^ aXor[mt]));
            #pragma unroll
            for (int np = 0; np < 4; np++)
                ldm_x4(bf[np], bBase + bRow[np] + (kbB ^ bXor[np]));
            #pragma unroll
            for (int mt = 0; mt < 4; mt++) {
                #pragma unroll
                for (int nt = 0; nt < 8; nt++) {
                    const uint32_t* bb = &bf[nt >> 1][(nt & 1) * 2];
                    mma16816(acc[mt][nt], af[mt], bb);
                }
            }
        }
        __syncthreads();   // protect buffer buf before its next overwrite
    }

    // ---- epilogue ----
    int rbase = m_off + (lane >> 2);
    int cbase = n_off + (lane & 3) * 2;

    int labR[8], labC[16];
    #pragma unroll
    for (int h = 0; h < 8; h++) labR[h] = sLabI[rbase + (h >> 1) * 16 + (h & 1) * 8];
    #pragma unroll
    for (int q = 0; q < 16; q++) labC[q] = sLabJ[cbase + (q >> 1) * 8 + (q & 1)];

    float zrp[8], prp[8], zcp[16], pcp[16];
    #pragma unroll
    for (int h = 0; h < 8; h++) { zrp[h] = 0.f; prp[h] = 0.f; }
    #pragma unroll
    for (int q = 0; q < 16; q++) { zcp[q] = 0.f; pcp[q] = 0.f; }

    #pragma unroll
    for (int mt = 0; mt < 4; mt++) {
        #pragma unroll
        for (int nt = 0; nt < 8; nt++) {
            #pragma unroll
            for (int k = 0; k < 4; k++) {
                int h = mt * 2 + ((k >> 1) & 1);
                int q = nt * 2 + (k & 1);
                int row = rbase + ((k >> 1) & 1) * 8 + mt * 16;
                int col = cbase + (k & 1) + nt * 8;
                float lg = 2.0f * acc[mt][nt][k];
                float e  = ex2(fmaf(lg, LOG2E, NEG2LOG2E));
                bool self = diag && (row == col);
                float ez = self ? 0.f : e;
                bool pos = (!self) && (labR[h] == labC[q]);
                float pz = pos ? lg : 0.f;
                zrp[h] += ez; prp[h] += pz;
                zcp[q] += ez; pcp[q] += pz;
            }
        }
    }

    // row reduce: lanes sharing a row differ in (lane&3)
    #pragma unroll
    for (int h = 0; h < 8; h++) {
        zrp[h] += __shfl_xor_sync(0xffffffffu, zrp[h], 1);
        zrp[h] += __shfl_xor_sync(0xffffffffu, zrp[h], 2);
        prp[h] += __shfl_xor_sync(0xffffffffu, prp[h], 1);
        prp[h] += __shfl_xor_sync(0xffffffffu, prp[h], 2);
        if ((lane & 3) == 0) {
            int row = rbase + (h >> 1) * 16 + (h & 1) * 8;
            atomicAdd(&sZr[row], zrp[h]);
            atomicAdd(&sPr[row], prp[h]);
        }
    }
    // col reduce: lanes sharing a col differ in (lane>>2)
    if (!diag) {
        #pragma unroll
        for (int q = 0; q < 16; q++) {
            zcp[q] += __shfl_xor_sync(0xffffffffu, zcp[q], 4);
            zcp[q] += __shfl_xor_sync(0xffffffffu, zcp[q], 8);
            zcp[q] += __shfl_xor_sync(0xffffffffu, zcp[q], 16);
            pcp[q] += __shfl_xor_sync(0xffffffffu, pcp[q], 4);
            pcp[q] += __shfl_xor_sync(0xffffffffu, pcp[q], 8);
            pcp[q] += __shfl_xor_sync(0xffffffffu, pcp[q], 16);
            if ((lane >> 2) == 0) {
                int col = cbase + (q >> 1) * 8 + (q & 1);
                atomicAdd(&sZc[col], zcp[q]);
                atomicAdd(&sPc[col], pcp[q]);
            }
        }
    }
    __syncthreads();

    atomicAdd(&g_Z[row0 + t], sZr[t]);
    atomicAdd(&g_P[row0 + t], sPr[t]);
    if (!diag) {
        atomicAdd(&g_Z[col0 + t], sZc[t]);
        atomicAdd(&g_P[col0 + t], sPc[t]);
    }
}

// ---------------- per-row loss, parallel reduction + fused scalar write ----------------
__global__ __launch_bounds__(256) void final_partial(const long long* __restrict__ labels,
                                                     float* __restrict__ out) {
    __shared__ float ssum[256];
    __shared__ float scnt[256];
    float sum = 0.f, cnt = 0.f;
    for (int i = blockIdx.x * 256 + threadIdx.x; i < B_ROWS; i += FGRID * 256) {
        int n = g_cnt[(int)labels[i] & 127] - 1;
        if (n > 0) {
            float per = g_P[i] / (float)n - 2.0f - logf(g_Z[i]);
            sum += -TEMP * per;
            cnt += 1.f;
        }
    }
    ssum[threadIdx.x] = sum; scnt[threadIdx.x] = cnt;
    __syncthreads();
    for (int sft = 128; sft; sft >>= 1) {
        if (threadIdx.x < sft) {
            ssum[threadIdx.x] += ssum[threadIdx.x + sft];
            scnt[threadIdx.x] += scnt[threadIdx.x + sft];
        }
        __syncthreads();
    }
    if (threadIdx.x == 0) {
        atomicAdd(&g_sum, ssum[0]);
        atomicAdd(&g_cntv, scnt[0]);
        __threadfence();
        unsigned int ticket = atomicAdd(&g_ticket, 1u);
        if (ticket == FGRID - 1) {
            float total = atomicAdd(&g_sum, 0.f);
            float nvald = atomicAdd(&g_cntv, 0.f);
            out[0] = total / fmaxf(nvald, 1.0f);
        }
    }
}

// ---------------------------------------------------------------------------
typedef CUresult (*tmap_encode_fn)(
    CUtensorMap*, CUtensorMapDataType, cuuint32_t, void*,
    const cuuint64_t*, const cuuint64_t*, const cuuint32_t*, const cuuint32_t*,
    CUtensorMapInterleave, CUtensorMapSwizzle, CUtensorMapL2promotion,
    CUtensorMapFloatOOBfill);

extern "C" void kernel_launch(void* const* d_in, const int* in_sizes, int n_in,
                              void* d_out, int out_size) {
    const float*     feat   = (const float*)d_in[0];
    const long long* labels = (const long long*)d_in[1];
    float*           out    = (float*)d_out;

    // Build the TMA descriptor for g_fb: 2D [1024 elems, 8192 rows], bf16,
    // box [64, 128], SW128. Driver entry fetched via runtime (no -lcuda link).
    void* fb_ptr = nullptr;
    cudaGetSymbolAddress(&fb_ptr, g_fb);
    void* fn_raw = nullptr;
    cudaDriverEntryPointQueryResult qres;
    cudaGetDriverEntryPointByVersion("cuTensorMapEncodeTiled", &fn_raw, 12000,
                                     cudaEnableDefault, &qres);
    CUtensorMap tmap;
    {
        tmap_encode_fn fn = (tmap_encode_fn)fn_raw;
        cuuint64_t dims[2]    = {(cuuint64_t)D_DIM, (cuuint64_t)B_ROWS};
        cuuint64_t strides[1] = {(cuuint64_t)D_DIM * 2};
        cuuint32_t box[2]     = {(cuuint32_t)BK, (cuuint32_t)TS};
        cuuint32_t estr[2]    = {1, 1};
        fn(&tmap, CU_TENSOR_MAP_DATA_TYPE_BFLOAT16, 2, fb_ptr,
           dims, strides, box, estr,
           CU_TENSOR_MAP_INTERLEAVE_NONE, CU_TENSOR_MAP_SWIZZLE_128B,
           CU_TENSOR_MAP_L2_PROMOTION_L2_128B, CU_TENSOR_MAP_FLOAT_OOB_FILL_NONE);
    }

    cudaFuncSetAttribute(gemm_kernel, cudaFuncAttributeMaxDynamicSharedMemorySize, SMEM_NEED);

    init_kernel<<<1, 256>>>();
    norm_kernel<<<B_ROWS, 256>>>(feat, labels);
    gemm_kernel<<<NTILES, 128, SMEM_NEED>>>(labels, tmap);
    final_partial<<<FGRID, 256>>>(labels, out);
}

// round 14
// speedup vs baseline: 1.0603x; 1.0017x over previous
#include <cuda_runtime.h>
#include <cuda.h>
#include <cuda_bf16.h>
#include <cstdint>

// Problem constants (B=8192, D=1024, T=0.5)
#define B_ROWS 8192
#define D_DIM  1024
#define TEMP   0.5f
#define LOG2E  1.44269504088896f
#define NEG2LOG2E (-2.88539008177793f)

#define TS      128                    // tile side
#define NB      (B_ROWS / TS)          // 64
#define NTILES  (NB * (NB + 1) / 2)    // 2080 upper-triangular tiles
#define BK      64                     // bf16 elems per row per stage (=128B)
#define NSTAGE  (D_DIM / BK)           // 16
#define FGRID   32                     // final reduction blocks
#define STAGE_BYTES (2 * TS * 128)     // A box + B box = 32KB

// dynamic smem layout (relative to 1024-aligned base)
#define OFF_LABI  0
#define OFF_LABJ  512
#define OFF_ZR    1024
#define OFF_PR    1536
#define OFF_ZC    2048
#define OFF_PC    2560
#define OFF_MBAR  3072                         // 2 x 8B mbarriers
#define OFF_A     4096                         // 2 x 16KB
#define OFF_B     (OFF_A + 2 * TS * 128)       // 36864, 2 x 16KB
#define SMEM_NEED (OFF_B + 2 * TS * 128 + 1024)

// device scratch (no allocation allowed)
__device__ __nv_bfloat16 g_fb[(size_t)B_ROWS * D_DIM];  // 16 MB normalized bf16
__device__ float g_Z[B_ROWS];
__device__ float g_P[B_ROWS];
__device__ int   g_cnt[128];
__device__ float g_sum;
__device__ float g_cntv;
__device__ unsigned int g_ticket;

// ---------------- helpers ----------------
__device__ __forceinline__ uint32_t smem_u32(const void* p) {
    uint32_t a;
    asm("{ .reg .u64 t; cvta.to.shared.u64 t, %1; cvt.u32.u64 %0, t; }" : "=r"(a) : "l"(p));
    return a;
}
__device__ __forceinline__ void mbar_init(uint32_t a, uint32_t c) {
    asm volatile("mbarrier.init.shared.b64 [%0], %1;" :: "r"(a), "r"(c) : "memory");
}
__device__ __forceinline__ void mbar_expect_tx(uint32_t a, uint32_t bytes) {
    asm volatile("mbarrier.arrive.expect_tx.shared.b64 _, [%0], %1;"
                 :: "r"(a), "r"(bytes) : "memory");
}
__device__ __forceinline__ void mbar_wait(uint32_t a, uint32_t parity) {
    asm volatile(
        "{\n\t.reg .pred P;\n\t"
        "W_%=:\n\t"
        "mbarrier.try_wait.parity.shared.b64 P, [%0], %1, 0x989680;\n\t"
        "@P bra.uni D_%=;\n\t"
        "bra.uni W_%=;\n\t"
        "D_%=:\n\t}"
        :: "r"(a), "r"(parity) : "memory");
}
__device__ __forceinline__ void tma_load_2d(uint32_t dst, const CUtensorMap* tmap,
                                            int cx, int cy, uint32_t mbar) {
    asm volatile(
        "cp.async.bulk.tensor.2d.shared::cta.global.tile.mbarrier::complete_tx::bytes "
        "[%0], [%1, {%2, %3}], [%4];"
        :: "r"(dst), "l"(tmap), "r"(cx), "r"(cy), "r"(mbar) : "memory");
}
__device__ __forceinline__ void ldm_x4(uint32_t* r, uint32_t addr) {
    asm volatile("ldmatrix.sync.aligned.m8n8.x4.shared.b16 {%0,%1,%2,%3}, [%4];"
                 : "=r"(r[0]), "=r"(r[1]), "=r"(r[2]), "=r"(r[3]) : "r"(addr));
}
__device__ __forceinline__ void mma16816(float* d, const uint32_t* a, const uint32_t* b) {
    asm volatile(
        "mma.sync.aligned.m16n8k16.row.col.f32.bf16.bf16.f32 "
        "{%0,%1,%2,%3}, {%4,%5,%6,%7}, {%8,%9}, {%0,%1,%2,%3};"
        : "+f"(d[0]), "+f"(d[1]), "+f"(d[2]), "+f"(d[3])
        : "r"(a[0]), "r"(a[1]), "r"(a[2]), "r"(a[3]), "r"(b[0]), "r"(b[1]));
}
__device__ __forceinline__ float ex2(float x) {
    float y; asm("ex2.approx.ftz.f32 %0, %1;" : "=f"(y) : "f"(x)); return y;
}

// ---------------- small kernels ----------------
__global__ void init_kernel() {
    int t = threadIdx.x;
    if (t < 128)  g_cnt[t] = 0;
    if (t == 128) { g_sum = 0.f; g_cntv = 0.f; g_ticket = 0u; }
}
// fused: L2-normalize + bf16 quantize + label histogram + Z/P zeroing
__global__ __launch_bounds__(256) void norm_kernel(const float* __restrict__ f,
                                                   const long long* __restrict__ labels) {
    int row = blockIdx.x;
    if (threadIdx.x == 0) {
        atomicAdd(&g_cnt[(int)labels[row] & 127], 1);
        g_Z[row] = 0.f;
        g_P[row] = 0.f;
    }
    const float4* src = (const float4*)(f + (size_t)row * D_DIM);
    float4 v = src[threadIdx.x];
    float ss = v.x * v.x + v.y * v.y + v.z * v.z + v.w * v.w;
    #pragma unroll
    for (int o = 16; o; o >>= 1) ss += __shfl_xor_sync(0xffffffffu, ss, o);
    __shared__ float red[8];
    if ((threadIdx.x & 31) == 0) red[threadIdx.x >> 5] = ss;
    __syncthreads();
    float tot = red[0] + red[1] + red[2] + red[3] + red[4] + red[5] + red[6] + red[7];
    float sc = rsqrtf(fmaxf(tot, 1e-24f));
    __nv_bfloat162* dst = (__nv_bfloat162*)(g_fb + (size_t)row * D_DIM);
    dst[threadIdx.x * 2 + 0] = __nv_bfloat162(__float2bfloat16_rn(v.x * sc), __float2bfloat16_rn(v.y * sc));
    dst[threadIdx.x * 2 + 1] = __nv_bfloat162(__float2bfloat16_rn(v.z * sc), __float2bfloat16_rn(v.w * sc));
}

// ---------------- main fused syrk + supcon epilogue (TMA + frag pipelining) ----------------
__global__ __launch_bounds__(128, 2) void gemm_kernel(const long long* __restrict__ labels,
                                                      const __grid_constant__ CUtensorMap tmap) {
    extern __shared__ char dsm[];
    uint32_t raw = smem_u32(dsm);
    uint32_t sb  = (raw + 1023) & ~1023u;
    char* s = dsm + (sb - raw);

    int t = threadIdx.x;
    int wid = t >> 5, lane = t & 31;

    // tile decode (bi <= bj)
    int b = blockIdx.x, bi = 0;
    while (b >= NB - bi) { b -= NB - bi; bi++; }
    int bj = bi + b;
    bool diag = (bi == bj);
    int row0 = bi * TS, col0 = bj * TS;

    int*   sLabI = (int*)(s + OFF_LABI);
    int*   sLabJ = (int*)(s + OFF_LABJ);
    float* sZr   = (float*)(s + OFF_ZR);
    float* sPr   = (float*)(s + OFF_PR);
    float* sZc   = (float*)(s + OFF_ZC);
    float* sPc   = (float*)(s + OFF_PC);

    sLabI[t] = (int)labels[row0 + t];
    sLabJ[t] = (int)labels[col0 + t];
    sZr[t] = 0.f; sPr[t] = 0.f; sZc[t] = 0.f; sPc[t] = 0.f;

    uint32_t mb0 = sb + OFF_MBAR, mb1 = sb + OFF_MBAR + 8;
    if (t == 0) { mbar_init(mb0, 1); mbar_init(mb1, 1); }
    __syncthreads();   // mbar init visible before first TMA

    // 4 warps, 2x2 grid of 64x64 warp tiles
    int m_off = (wid >> 1) * 64;
    int n_off = (wid & 1) * 64;

    uint32_t aRow[4], aXor[4];
    {
        int r = m_off + (lane & 15);
        #pragma unroll
        for (int mt = 0; mt < 4; mt++) {
            uint32_t rb = (uint32_t)(r + mt * 16) * 128;
            aRow[mt] = rb; aXor[mt] = (rb >> 3) & 0x70;
        }
    }
    uint32_t aK8 = ((lane >> 4) & 1) * 16;   // bytes
    uint32_t bRow[4], bXor[4];
    {
        int n = n_off + (lane & 7) + ((lane >> 4) << 3);
        #pragma unroll
        for (int np = 0; np < 4; np++) {
            uint32_t rb = (uint32_t)(n + np * 16) * 128;
            bRow[np] = rb; bXor[np] = (rb >> 3) & 0x70;
        }
    }
    uint32_t bK8 = ((lane >> 3) & 1) * 16;   // bytes

    float acc[4][8][4];
    #pragma unroll
    for (int mt = 0; mt < 4; mt++)
        #pragma unroll
        for (int nt = 0; nt < 8; nt++)
            #pragma unroll
            for (int k = 0; k < 4; k++) acc[mt][nt][k] = 0.f;

    // stage 0 into buffer 0
    if (t == 0) {
        mbar_expect_tx(mb0, STAGE_BYTES);
        tma_load_2d(sb + OFF_A, &tmap, 0, row0, mb0);
        tma_load_2d(sb + OFF_B, &tmap, 0, col0, mb0);
    }
    int ph0 = 0, ph1 = 0;

    for (int st = 0; st < NSTAGE; st++) {
        int buf = st & 1;
        // prefetch next stage into the other buffer; trailing __syncthreads of
        // stage st-1 guarantees all warps finished reading it.
        if (st + 1 < NSTAGE && t == 0) {
            uint32_t nb = buf ^ 1;
            uint32_t mbn = nb ? mb1 : mb0;
            uint32_t ao = sb + OFF_A + nb * (TS * 128);
            uint32_t bo = sb + OFF_B + nb * (TS * 128);
            int kc = (st + 1) * BK;
            mbar_expect_tx(mbn, STAGE_BYTES);
            tma_load_2d(ao, &tmap, kc, row0, mbn);
            tma_load_2d(bo, &tmap, kc, col0, mbn);
        }
        // wait for current stage's data
        if (buf) { mbar_wait(mb1, ph1); ph1 ^= 1; }
        else     { mbar_wait(mb0, ph0); ph0 ^= 1; }

        uint32_t aBase = sb + OFF_A + buf * (TS * 128);
        uint32_t bBase = sb + OFF_B + buf * (TS * 128);

        // fragment double-buffering: load ks+1 fragments before ks MMAs so
        // LDSM latency overlaps the 32-MMA chain.
        uint32_t af[2][4][4], bf[2][4][4];
        {
            uint32_t kbA = aK8, kbB = bK8;   // ks = 0
            #pragma unroll
            for (int mt = 0; mt < 4; mt++)
                ldm_x4(af[0][mt], aBase + aRow[mt] + (kbA ^ aXor[mt]));
            #pragma unroll
            for (int np = 0; np < 4; np++)
                ldm_x4(bf[0][np], bBase + bRow[np] + (kbB ^ bXor[np]));
        }
        #pragma unroll
        for (int ks = 0; ks < 4; ks++) {
            int cur = ks & 1;
            if (ks < 3) {
                int nxt = cur ^ 1;
                uint32_t kbA = (uint32_t)((ks + 1) * 32) + aK8;
                uint32_t kbB = (uint32_t)((ks + 1) * 32) + bK8;
                #pragma unroll
                for (int mt = 0; mt < 4; mt++)
                    ldm_x4(af[nxt][mt], aBase + aRow[mt] + (kbA ^ aXor[mt]));
                #pragma unroll
                for (int np = 0; np < 4; np++)
                    ldm_x4(bf[nxt][np], bBase + bRow[np] + (kbB ^ bXor[np]));
            }
            #pragma unroll
            for (int mt = 0; mt < 4; mt++) {
                #pragma unroll
                for (int nt = 0; nt < 8; nt++) {
                    const uint32_t* bb = &bf[cur][nt >> 1][(nt & 1) * 2];
                    mma16816(acc[mt][nt], af[cur][mt], bb);
                }
            }
        }
        __syncthreads();   // protect buffer buf before its next overwrite
    }

    // ---- epilogue ----
    int rbase = m_off + (lane >> 2);
    int cbase = n_off + (lane & 3) * 2;

    int labR[8], labC[16];
    #pragma unroll
    for (int h = 0; h < 8; h++) labR[h] = sLabI[rbase + (h >> 1) * 16 + (h & 1) * 8];
    #pragma unroll
    for (int q = 0; q < 16; q++) labC[q] = sLabJ[cbase + (q >> 1) * 8 + (q & 1)];

    float zrp[8], prp[8], zcp[16], pcp[16];
    #pragma unroll
    for (int h = 0; h < 8; h++) { zrp[h] = 0.f; prp[h] = 0.f; }
    #pragma unroll
    for (int q = 0; q < 16; q++) { zcp[q] = 0.f; pcp[q] = 0.f; }

    #pragma unroll
    for (int mt = 0; mt < 4; mt++) {
        #pragma unroll
        for (int nt = 0; nt < 8; nt++) {
            #pragma unroll
            for (int k = 0; k < 4; k++) {
                int h = mt * 2 + ((k >> 1) & 1);
                int q = nt * 2 + (k & 1);
                int row = rbase + ((k >> 1) & 1) * 8 + mt * 16;
                int col = cbase + (k & 1) + nt * 8;
                float lg = 2.0f * acc[mt][nt][k];
                float e  = ex2(fmaf(lg, LOG2E, NEG2LOG2E));
                bool self = diag && (row == col);
                float ez = self ? 0.f : e;
                bool pos = (!self) && (labR[h] == labC[q]);
                float pz = pos ? lg : 0.f;
                zrp[h] += ez; prp[h] += pz;
                zcp[q] += ez; pcp[q] += pz;
            }
        }
    }

    // row reduce: lanes sharing a row differ in (lane&3)
    #pragma unroll
    for (int h = 0; h < 8; h++) {
        zrp[h] += __shfl_xor_sync(0xffffffffu, zrp[h], 1);
        zrp[h] += __shfl_xor_sync(0xffffffffu, zrp[h], 2);
        prp[h] += __shfl_xor_sync(0xffffffffu, prp[h], 1);
        prp[h] += __shfl_xor_sync(0xffffffffu, prp[h], 2);
        if ((lane & 3) == 0) {
            int row = rbase + (h >> 1) * 16 + (h & 1) * 8;
            atomicAdd(&sZr[row], zrp[h]);
            atomicAdd(&sPr[row], prp[h]);
        }
    }
    // col reduce: lanes sharing a col differ in (lane>>2)
    if (!diag) {
        #pragma unroll
        for (int q = 0; q < 16; q++) {
            zcp[q] += __shfl_xor_sync(0xffffffffu, zcp[q], 4);
            zcp[q] += __shfl_xor_sync(0xffffffffu, zcp[q], 8);
            zcp[q] += __shfl_xor_sync(0xffffffffu, zcp[q], 16);
            pcp[q] += __shfl_xor_sync(0xffffffffu, pcp[q], 4);
            pcp[q] += __shfl_xor_sync(0xffffffffu, pcp[q], 8);
            pcp[q] += __shfl_xor_sync(0xffffffffu, pcp[q], 16);
            if ((lane >> 2) == 0) {
                int col = cbase + (q >> 1) * 8 + (q & 1);
                atomicAdd(&sZc[col], zcp[q]);
                atomicAdd(&sPc[col], pcp[q]);
            }
        }
    }
    __syncthreads();

    atomicAdd(&g_Z[row0 + t], sZr[t]);
    atomicAdd(&g_P[row0 + t], sPr[t]);
    if (!diag) {
        atomicAdd(&g_Z[col0 + t], sZc[t]);
        atomicAdd(&g_P[col0 + t], sPc[t]);
    }
}

// ---------------- per-row loss, parallel reduction + fused scalar write ----------------
__global__ __launch_bounds__(256) void final_partial(const long long* __restrict__ labels,
                                                     float* __restrict__ out) {
    __shared__ float ssum[256];
    __shared__ float scnt[256];
    float sum = 0.f, cnt = 0.f;
    for (int i = blockIdx.x * 256 + threadIdx.x; i < B_ROWS; i += FGRID * 256) {
        int n = g_cnt[(int)labels[i] & 127] - 1;
        if (n > 0) {
            float per = g_P[i] / (float)n - 2.0f - logf(g_Z[i]);
            sum += -TEMP * per;
            cnt += 1.f;
        }
    }
    ssum[threadIdx.x] = sum; scnt[threadIdx.x] = cnt;
    __syncthreads();
    for (int sft = 128; sft; sft >>= 1) {
        if (threadIdx.x < sft) {
            ssum[threadIdx.x] += ssum[threadIdx.x + sft];
            scnt[threadIdx.x] += scnt[threadIdx.x + sft];
        }
        __syncthreads();
    }
    if (threadIdx.x == 0) {
        atomicAdd(&g_sum, ssum[0]);
        atomicAdd(&g_cntv, scnt[0]);
        __threadfence();
        unsigned int ticket = atomicAdd(&g_ticket, 1u);
        if (ticket == FGRID - 1) {
            float total = atomicAdd(&g_sum, 0.f);
            float nvald = atomicAdd(&g_cntv, 0.f);
            out[0] = total / fmaxf(nvald, 1.0f);
        }
    }
}

// ---------------------------------------------------------------------------
typedef CUresult (*tmap_encode_fn)(
    CUtensorMap*, CUtensorMapDataType, cuuint32_t, void*,
    const cuuint64_t*, const cuuint64_t*, const cuuint32_t*, const cuuint32_t*,
    CUtensorMapInterleave, CUtensorMapSwizzle, CUtensorMapL2promotion,
    CUtensorMapFloatOOBfill);

extern "C" void kernel_launch(void* const* d_in, const int* in_sizes, int n_in,
                              void* d_out, int out_size) {
    const float*     feat   = (const float*)d_in[0];
    const long long* labels = (const long long*)d_in[1];
    float*           out    = (float*)d_out;

    // Build the TMA descriptor for g_fb: 2D [1024 elems, 8192 rows], bf16,
    // box [64, 128], SW128. Driver entry fetched via runtime (no -lcuda link).
    void* fb_ptr = nullptr;
    cudaGetSymbolAddress(&fb_ptr, g_fb);
    void* fn_raw = nullptr;
    cudaDriverEntryPointQueryResult qres;
    cudaGetDriverEntryPointByVersion("cuTensorMapEncodeTiled", &fn_raw, 12000,
                                     cudaEnableDefault, &qres);
    CUtensorMap tmap;
    {
        tmap_encode_fn fn = (tmap_encode_fn)fn_raw;
        cuuint64_t dims[2]    = {(cuuint64_t)D_DIM, (cuuint64_t)B_ROWS};
        cuuint64_t strides[1] = {(cuuint64_t)D_DIM * 2};
        cuuint32_t box[2]     = {(cuuint32_t)BK, (cuuint32_t)TS};
        cuuint32_t estr[2]    = {1, 1};
        fn(&tmap, CU_TENSOR_MAP_DATA_TYPE_BFLOAT16, 2, fb_ptr,
           dims, strides, box, estr,
           CU_TENSOR_MAP_INTERLEAVE_NONE, CU_TENSOR_MAP_SWIZZLE_128B,
           CU_TENSOR_MAP_L2_PROMOTION_L2_128B, CU_TENSOR_MAP_FLOAT_OOB_FILL_NONE);
    }

    cudaFuncSetAttribute(gemm_kernel, cudaFuncAttributeMaxDynamicSharedMemorySize, SMEM_NEED);

    init_kernel<<<1, 256>>>();
    norm_kernel<<<B_ROWS, 256>>>(feat, labels);
    gemm_kernel<<<NTILES, 128, SMEM_NEED>>>(labels, tmap);
    final_partial<<<FGRID, 256>>>(labels, out);
}